// round 9
// baseline (speedup 1.0000x reference)
#include <cuda_runtime.h>
#include <cuda_bf16.h>

// Problem constants
#define BB   512
#define LL   16384
#define NW   (LL - 5 + 1)          // 16380 windows

// Tiling: warps overlap by 4 elements; 124 windows per warp, no halo loads.
#define TPB  128                   // 4 warps
#define WWIN 124                   // windows per warp (lanes 0..30 x 4)
#define CW   (4 * WWIN)            // 496 windows per block
#define NWCH ((NW + CW - 1) / CW)  // 34 window chunks
#define BC   16                    // batches per block
#define NBCH (BB / BC)             // 32 batch chunks
#define NBLK (NWCH * NBCH)         // 1088 blocks
#define NBLKP 1152                 // padded partial count (multiple of 128)
#define NVW  512                   // validity words: 16380 bits -> 512 words

// Deterministic scratch (no cudaMalloc allowed).
__device__ float        g_sq_blk[NBLKP];  // per-block sq partial (padding stays 0)
__device__ unsigned     g_vld_or[NVW];    // bit-per-window validity (OR-accum);
                                          // zeroed by last block each launch
__device__ unsigned int g_done;           // arrival counter; atomicInc wraps
                                          // at NBLK-1 -> self-resets per launch

__device__ __forceinline__ float sigm(float x0, float x1) {
    // softmax(x)[...,1] == sigmoid(x1-x0) == 1/(1+exp(x0-x1))
    return __fdividef(1.0f, 1.0f + __expf(x0 - x1));
}

// Per-window math. smm = packed sliding sum (msum + 32*tsum), spm = sum(p*m),
// sq = sum(p^2*m). msum integer-valued => pvar = sq/denom - pmean^2,
// tvar = tmean*(1-tmean). Matches reference up to f32 rounding.
#define WIN(K, ACC) { \
    float stm   = floorf(smm * 0.03125f); \
    float sm    = fmaf(-32.0f, stm, smm); \
    float denom = fmaxf(sm, 1.0f); \
    float rd    = __fdividef(1.0f, denom); \
    float pmean = spm * rd; \
    float tmean = stm * rd; \
    float pvar  = fmaf(-pmean, pmean, sq * rd); \
    float tvar  = fmaf(-tmean, tmean, tmean); \
    float d     = pvar - tvar; \
    ACC = fmaf(d, d, ACC); \
    if (sm > 0.0f) vmask |= (1u << (K)); \
}

__global__ __launch_bounds__(TPB, 8)
void bcl_fused(const float* __restrict__ pred,
               const int*   __restrict__ tgt,
               const int*   __restrict__ msk,
               float*       __restrict__ out)
{
    const int lane = threadIdx.x & 31;
    const int wrp  = threadIdx.x >> 5;
    const int seg  = blockIdx.x * CW + wrp * WWIN;  // warp's first elem/window
    const int bch  = blockIdx.y;
    const int eo   = seg + 4 * lane;                // lane's first elem/window

    // Branch-free OOB handling: clamp the load offset (iter-invariant),
    // zero the mask for OOB lanes -> exact zero contribution.
    const bool lane_ok = (eo < LL);                 // lane's 4 elems in bounds
    const int  off = lane_ok ? (4 * lane) : (LL - 4 - seg);  // elem offset
    const int  o2  = off / 2;                       // float4-pair index
    const int  o4  = off / 4;                       // int4 index
    const int  gm  = lane_ok ? -1 : 0;              // mask gate

    float acc0 = 0.f, acc1 = 0.f, acc2 = 0.f, acc3 = 0.f;
    unsigned vmask = 0u;

    const size_t eb0 = (size_t)(bch * BC) * LL + seg;
    const float4* fp4 = (const float4*)(pred + 2 * eb0);
    const int4*   t4p = (const int4*)(tgt + eb0);
    const int4*   m4p = (const int4*)(msk + eb0);

    for (int bi = 0; bi < BC; bi++) {
        // Own loads: lane owns 4 consecutive elems (coalesced).
        float4 v0 = fp4[o2];
        float4 v1 = fp4[o2 + 1];
        int4   tv = t4p[o4];
        int4   mv = m4p[o4];
        mv.x &= gm; mv.y &= gm; mv.z &= gm; mv.w &= gm;

        // Derived: p = sigmoid; mm = m + 32*(t&m); pm = p*m; q = p^2*m
        float p0 = sigm(v0.x, v0.y), p1 = sigm(v0.z, v0.w);
        float p2 = sigm(v1.x, v1.y), p3 = sigm(v1.z, v1.w);
        float mm0 = (float)(mv.x + ((tv.x & mv.x) << 5));
        float mm1 = (float)(mv.y + ((tv.y & mv.y) << 5));
        float mm2 = (float)(mv.z + ((tv.z & mv.z) << 5));
        float mm3 = (float)(mv.w + ((tv.w & mv.w) << 5));
        float pm0 = mv.x ? p0 : 0.f, pm1 = mv.y ? p1 : 0.f;
        float pm2 = mv.z ? p2 : 0.f, pm3 = mv.w ? p3 : 0.f;
        float q0 = p0 * pm0, q1 = p1 * pm1, q2 = p2 * pm2, q3 = p3 * pm3;

        // Neighbor (lane+1) quantities via shfl. Lane 31 is halo-only:
        // it receives its own values back (finite), results discarded.
        float nmm0 = __shfl_down_sync(0xffffffffu, mm0, 1);
        float nmm1 = __shfl_down_sync(0xffffffffu, mm1, 1);
        float nmm2 = __shfl_down_sync(0xffffffffu, mm2, 1);
        float nmm3 = __shfl_down_sync(0xffffffffu, mm3, 1);
        float npm0 = __shfl_down_sync(0xffffffffu, pm0, 1);
        float npm1 = __shfl_down_sync(0xffffffffu, pm1, 1);
        float npm2 = __shfl_down_sync(0xffffffffu, pm2, 1);
        float npm3 = __shfl_down_sync(0xffffffffu, pm3, 1);
        float nq0  = __shfl_down_sync(0xffffffffu, q0, 1);
        float nq1  = __shfl_down_sync(0xffffffffu, q1, 1);
        float nq2  = __shfl_down_sync(0xffffffffu, q2, 1);
        float nq3  = __shfl_down_sync(0xffffffffu, q3, 1);

        // Sliding window-5 sums over {own0..3, n0..3}, incremental.
        float smm = mm0 + mm1 + mm2 + mm3 + nmm0;
        float spm = pm0 + pm1 + pm2 + pm3 + npm0;
        float sq  = q0 + q1 + q2 + q3 + nq0;
        WIN(0, acc0)
        smm += nmm1 - mm0; spm += npm1 - pm0; sq += nq1 - q0;
        WIN(1, acc1)
        smm += nmm2 - mm1; spm += npm2 - pm1; sq += nq2 - q1;
        WIN(2, acc2)
        smm += nmm3 - mm2; spm += npm3 - pm2; sq += nq3 - q2;
        WIN(3, acc3)

        fp4 += (LL / 2); t4p += (LL / 4); m4p += (LL / 4);
    }

    // Window gating: lane 31 is halo-only (its windows belong to the next
    // warp); windows >= NW don't exist.
    unsigned amask = 0u;
    if (lane < 31) {
        if (eo + 0 < NW) amask |= 1u;
        if (eo + 1 < NW) amask |= 2u;
        if (eo + 2 < NW) amask |= 4u;
        if (eo + 3 < NW) amask |= 8u;
    }
    vmask &= amask;
    if (!(amask & 1u)) acc0 = 0.f;
    if (!(amask & 2u)) acc1 = 0.f;
    if (!(amask & 4u)) acc2 = 0.f;
    if (!(amask & 8u)) acc3 = 0.f;

    // Validity: set this lane's window bits in the global bit array.
    // Integer atomicOr (RED.OR, no return) is order-independent ->
    // deterministic. Typically 1 atomic per thread.
    if (vmask) {
        unsigned word = (unsigned)eo >> 5, sh = (unsigned)eo & 31u;
        unsigned long long wide = (unsigned long long)vmask << sh;
        unsigned lo = (unsigned)wide, hi = (unsigned)(wide >> 32);
        atomicOr(&g_vld_or[word], lo);
        if (hi) atomicOr(&g_vld_or[word + 1], hi);
    }
    __threadfence();   // this thread's REDs visible before its barrier arrival

    // In-block deterministic reduction of sq -> one float per block.
    float a = (acc0 + acc1) + (acc2 + acc3);
    a += __shfl_xor_sync(0xffffffffu, a, 16);
    a += __shfl_xor_sync(0xffffffffu, a, 8);
    a += __shfl_xor_sync(0xffffffffu, a, 4);
    a += __shfl_xor_sync(0xffffffffu, a, 2);
    a += __shfl_xor_sync(0xffffffffu, a, 1);
    __shared__ float s_red[4];
    __shared__ unsigned s_last;
    if (lane == 0) s_red[wrp] = a;
    __syncthreads();
    if (threadIdx.x == 0) {
        g_sq_blk[bch * NWCH + blockIdx.x] =
            (s_red[0] + s_red[1]) + (s_red[2] + s_red[3]);
        __threadfence();   // partial visible before arrival
        // Wrapping arrival counter: self-resets to 0 after NBLK increments.
        unsigned old = atomicInc(&g_done, NBLK - 1);
        s_last = (old == NBLK - 1) ? 1u : 0u;
    }
    __syncthreads();
    if (!s_last) return;

    // ---- Last block: final reduction (4.5 KB sq + 2 KB validity) ----
    __threadfence();       // acquire: all other blocks' fenced writes visible
    const int t = threadIdx.x;

    float s = 0.f;
#pragma unroll
    for (int i = 0; i < NBLKP / 128; i++)
        s += g_sq_blk[t + 128 * i];            // padding reads are 0

    uint4 vv = ((const uint4*)g_vld_or)[t];    // 512 words / 128 thr
    int c = __popc(vv.x) + __popc(vv.y) + __popc(vv.z) + __popc(vv.w);
    // Zero validity accumulator for the next graph replay.
    ((uint4*)g_vld_or)[t] = make_uint4(0u, 0u, 0u, 0u);

    // Block reduce s and c.
    s += __shfl_xor_sync(0xffffffffu, s, 16);
    s += __shfl_xor_sync(0xffffffffu, s, 8);
    s += __shfl_xor_sync(0xffffffffu, s, 4);
    s += __shfl_xor_sync(0xffffffffu, s, 2);
    s += __shfl_xor_sync(0xffffffffu, s, 1);
    c += __shfl_xor_sync(0xffffffffu, c, 16);
    c += __shfl_xor_sync(0xffffffffu, c, 8);
    c += __shfl_xor_sync(0xffffffffu, c, 4);
    c += __shfl_xor_sync(0xffffffffu, c, 2);
    c += __shfl_xor_sync(0xffffffffu, c, 1);
    __shared__ float fs[4];
    __shared__ int   fc[4];
    if (lane == 0) { fs[wrp] = s; fc[wrp] = c; }
    __syncthreads();
    if (t == 0) {
        float S = (fs[0] + fs[1]) + (fs[2] + fs[3]);
        int   C = (fc[0] + fc[1]) + (fc[2] + fc[3]);
        out[0] = S * (1.0f / (float)BB) / fmaxf((float)C, 1.0f);
    }
}

extern "C" void kernel_launch(void* const* d_in, const int* in_sizes, int n_in,
                              void* d_out, int out_size)
{
    const float* pred = (const float*)d_in[0];   // [512, 16384, 2] f32
    const int*   tgt  = (const int*)d_in[1];     // [512, 16384] i32
    const int*   msk  = (const int*)d_in[2];     // [512, 16384] i32

    dim3 grid(NWCH, NBCH);                        // 34 x 32 = 1088 blocks
    bcl_fused<<<grid, TPB>>>(pred, tgt, msk, (float*)d_out);
}

// round 10
// speedup vs baseline: 1.1379x; 1.1379x over previous
#include <cuda_runtime.h>
#include <cuda_bf16.h>

// Problem constants
#define BB   512
#define LL   16384
#define NW   (LL - 5 + 1)          // 16380 windows

// Tiling: 8 windows per lane, 256 elements/windows per warp (aligned).
#define TPB  128                   // 4 warps
#define SEGW 256                   // elements per warp
#define CW   1024                  // windows per block
#define NWCH (LL / CW)             // 16 window chunks
#define BC   8                     // batches per block
#define NBCH (BB / BC)             // 64 batch chunks
#define NBLK (NWCH * NBCH)         // 1024 blocks -> single wave
#define NVW  512                   // validity words: 16380 bits

// Deterministic scratch (no cudaMalloc allowed).
__device__ float        g_sq_blk[NBLK];   // per-block sq partial (4 KB)
__device__ unsigned     g_vld_or[NVW];    // bit-per-window validity (OR-accum);
                                          // zeroed by last block each launch
__device__ unsigned int g_done;           // arrival counter; atomicInc wraps
                                          // at NBLK-1 -> self-resets per launch

__device__ __forceinline__ float sigm(float x0, float x1) {
    // softmax(x)[...,1] == sigmoid(x1-x0) == 1/(1+exp(x0-x1))
    return __fdividef(1.0f, 1.0f + __expf(x0 - x1));
}

__global__ __launch_bounds__(TPB, 7)
void bcl_fused(const float* __restrict__ pred,
               const int*   __restrict__ tgt,
               const int*   __restrict__ msk,
               float*       __restrict__ out)
{
    const int lane = threadIdx.x & 31;
    const int wrp  = threadIdx.x >> 5;
    const int seg  = blockIdx.x * CW + wrp * SEGW;  // warp's first elem/window
    const int bch  = blockIdx.y;
    const int eo   = seg + 8 * lane;                // lane's first elem/window
    const bool blk_halo = (seg + SEGW) < LL;        // halo elems exist?
    const int hofs4 = blk_halo ? (SEGW / 2) : 0;    // float4 idx of elem seg+256
    const int hofsT = blk_halo ? (SEGW / 4) : 0;    // int4 idx of elem seg+256

    float accA = 0.f, accB = 0.f;                   // windows k<4 / k>=4
    unsigned vmask = 0u;

    const size_t eb0 = (size_t)(bch * BC) * LL + seg;
    const float4* fp4 = (const float4*)(pred + 2 * eb0);
    const int4*   t4p = (const int4*)(tgt + eb0);
    const int4*   m4p = (const int4*)(msk + eb0);

    for (int bi = 0; bi < BC; bi++) {
        // Own loads: lane owns 8 consecutive elems (coalesced, 8 loads in flight).
        float4 v0 = fp4[4 * lane];
        float4 v1 = fp4[4 * lane + 1];
        float4 v2 = fp4[4 * lane + 2];
        float4 v3 = fp4[4 * lane + 3];
        int4   tv0 = t4p[2 * lane],     tv1 = t4p[2 * lane + 1];
        int4   mv0 = m4p[2 * lane],     mv1 = m4p[2 * lane + 1];
        // Warp-edge halo (uniform broadcast loads; used only by lane 31).
        float4 hv0 = fp4[hofs4], hv1 = fp4[hofs4 + 1];
        int4   htv = t4p[hofsT], hmv = m4p[hofsT];
        if (!blk_halo) { hmv.x = 0; hmv.y = 0; hmv.z = 0; hmv.w = 0; }

        // Derived per element: p = sigmoid; mm = m + 32*(t&m); pm = p*m; q = p^2*m
        float p[8], mm[8], pm[8], q[8];
        p[0] = sigm(v0.x, v0.y); p[1] = sigm(v0.z, v0.w);
        p[2] = sigm(v1.x, v1.y); p[3] = sigm(v1.z, v1.w);
        p[4] = sigm(v2.x, v2.y); p[5] = sigm(v2.z, v2.w);
        p[6] = sigm(v3.x, v3.y); p[7] = sigm(v3.z, v3.w);
        const int tt[8] = {tv0.x, tv0.y, tv0.z, tv0.w, tv1.x, tv1.y, tv1.z, tv1.w};
        const int mi[8] = {mv0.x, mv0.y, mv0.z, mv0.w, mv1.x, mv1.y, mv1.z, mv1.w};
#pragma unroll
        for (int e = 0; e < 8; e++) {
            mm[e] = (float)(mi[e] + ((tt[e] & mi[e]) << 5));
            pm[e] = mi[e] ? p[e] : 0.f;
            q[e]  = p[e] * pm[e];
        }

        // Neighbor's first 4 derived values via shfl (convergent).
        float nmm[4], npm[4], nq[4];
#pragma unroll
        for (int k = 0; k < 4; k++) {
            nmm[k] = __shfl_down_sync(0xffffffffu, mm[k], 1);
            npm[k] = __shfl_down_sync(0xffffffffu, pm[k], 1);
            nq[k]  = __shfl_down_sync(0xffffffffu, q[k], 1);
        }
        // Lane 31 patches its halo from the warp-edge loads.
        if (lane == 31) {
            float hp[4];
            hp[0] = sigm(hv0.x, hv0.y); hp[1] = sigm(hv0.z, hv0.w);
            hp[2] = sigm(hv1.x, hv1.y); hp[3] = sigm(hv1.z, hv1.w);
            const int ht[4] = {htv.x, htv.y, htv.z, htv.w};
            const int hm[4] = {hmv.x, hmv.y, hmv.z, hmv.w};
#pragma unroll
            for (int k = 0; k < 4; k++) {
                nmm[k] = (float)(hm[k] + ((ht[k] & hm[k]) << 5));
                npm[k] = hm[k] ? hp[k] : 0.f;
                nq[k]  = hp[k] * npm[k];
            }
        }

        // Sliding window-5 over 12 elems {mm[0..7], nmm[0..3]}, incremental.
        float smm = mm[0] + mm[1] + mm[2] + mm[3] + mm[4];
        float spm = pm[0] + pm[1] + pm[2] + pm[3] + pm[4];
        float sq  = q[0]  + q[1]  + q[2]  + q[3]  + q[4];
#pragma unroll
        for (int k = 0; k < 8; k++) {
            if (k > 0) {
                float am = (k + 4 < 8) ? mm[k + 4] : nmm[k - 4];
                float ap = (k + 4 < 8) ? pm[k + 4] : npm[k - 4];
                float aq = (k + 4 < 8) ? q[k + 4]  : nq[k - 4];
                smm += am - mm[k - 1];
                spm += ap - pm[k - 1];
                sq  += aq - q[k - 1];
            }
            // msum integer-valued: pvar = sq/denom - pmean^2; tvar = tmean(1-tmean)
            float stm   = floorf(smm * 0.03125f);
            float sm    = fmaf(-32.0f, stm, smm);
            float denom = fmaxf(sm, 1.0f);
            float rd    = __fdividef(1.0f, denom);
            float pmean = spm * rd;
            float tmean = stm * rd;
            float pvar  = fmaf(-pmean, pmean, sq * rd);
            float tvar  = fmaf(-tmean, tmean, tmean);
            float d     = pvar - tvar;
            if (k < 4) accA = fmaf(d, d, accA);
            else       accB = fmaf(d, d, accB);
            if (sm > 0.f) vmask |= (1u << k);
        }

        fp4 += (LL / 2); t4p += (LL / 4); m4p += (LL / 4);
    }

    // Tail gating: the ONLY OOB windows are eo=16376 (lane 31, warp 3,
    // block 15), positions k=4..7 — exactly accB.
    if (eo + 4 >= NW) { accB = 0.f; vmask &= 0x0Fu; }

    // Validity: one atomicOr per thread (RED.OR, order-independent ->
    // deterministic). eo is a multiple of 8, so the 8 bits never straddle.
    if (vmask)
        atomicOr(&g_vld_or[(unsigned)eo >> 5], vmask << ((unsigned)eo & 31u));
    __threadfence();   // this thread's REDs visible before block arrival

    // In-block deterministic reduction of sq -> one float per block.
    float a = accA + accB;
    a += __shfl_xor_sync(0xffffffffu, a, 16);
    a += __shfl_xor_sync(0xffffffffu, a, 8);
    a += __shfl_xor_sync(0xffffffffu, a, 4);
    a += __shfl_xor_sync(0xffffffffu, a, 2);
    a += __shfl_xor_sync(0xffffffffu, a, 1);
    __shared__ float s_red[4];
    __shared__ unsigned s_last;
    if (lane == 0) s_red[wrp] = a;
    __syncthreads();
    if (threadIdx.x == 0) {
        g_sq_blk[bch * NWCH + blockIdx.x] =
            (s_red[0] + s_red[1]) + (s_red[2] + s_red[3]);
        __threadfence();   // partial visible before arrival
        // Wrapping arrival counter: self-resets to 0 after NBLK increments.
        unsigned old = atomicInc(&g_done, NBLK - 1);
        s_last = (old == NBLK - 1) ? 1u : 0u;
    }
    __syncthreads();
    if (!s_last) return;

    // ---- Last block: final reduction (4 KB sq + 2 KB validity) ----
    __threadfence();       // acquire: all other blocks' fenced writes visible
    const int t = threadIdx.x;

    float s = 0.f;
    const float4* sq4 = (const float4*)g_sq_blk;   // 1024 floats = 256 float4
#pragma unroll
    for (int i = 0; i < 2; i++) {
        float4 v = sq4[t + 128 * i];
        s += (v.x + v.y) + (v.z + v.w);
    }
    uint4 vv = ((const uint4*)g_vld_or)[t];        // 512 words / 128 thr
    int c = __popc(vv.x) + __popc(vv.y) + __popc(vv.z) + __popc(vv.w);
    // Zero validity accumulator for the next graph replay.
    ((uint4*)g_vld_or)[t] = make_uint4(0u, 0u, 0u, 0u);

    // Block reduce s and c.
    s += __shfl_xor_sync(0xffffffffu, s, 16);
    s += __shfl_xor_sync(0xffffffffu, s, 8);
    s += __shfl_xor_sync(0xffffffffu, s, 4);
    s += __shfl_xor_sync(0xffffffffu, s, 2);
    s += __shfl_xor_sync(0xffffffffu, s, 1);
    c += __shfl_xor_sync(0xffffffffu, c, 16);
    c += __shfl_xor_sync(0xffffffffu, c, 8);
    c += __shfl_xor_sync(0xffffffffu, c, 4);
    c += __shfl_xor_sync(0xffffffffu, c, 2);
    c += __shfl_xor_sync(0xffffffffu, c, 1);
    __shared__ float fs[4];
    __shared__ int   fc[4];
    if (lane == 0) { fs[wrp] = s; fc[wrp] = c; }
    __syncthreads();
    if (t == 0) {
        float S = (fs[0] + fs[1]) + (fs[2] + fs[3]);
        int   C = (fc[0] + fc[1]) + (fc[2] + fc[3]);
        out[0] = S * (1.0f / (float)BB) / fmaxf((float)C, 1.0f);
    }
}

extern "C" void kernel_launch(void* const* d_in, const int* in_sizes, int n_in,
                              void* d_out, int out_size)
{
    const float* pred = (const float*)d_in[0];   // [512, 16384, 2] f32
    const int*   tgt  = (const int*)d_in[1];     // [512, 16384] i32
    const int*   msk  = (const int*)d_in[2];     // [512, 16384] i32

    dim3 grid(NWCH, NBCH);                        // 16 x 64 = 1024 blocks
    bcl_fused<<<grid, TPB>>>(pred, tgt, msk, (float*)d_out);
}

// round 11
// speedup vs baseline: 1.1491x; 1.0099x over previous
#include <cuda_runtime.h>
#include <cuda_bf16.h>

// Problem constants
#define BB   512
#define LL   16384
#define NW   (LL - 5 + 1)          // 16380 windows

// Tiling: 8 windows per lane, 256 elements per warp.
#define TPB  128                   // 4 warps
#define SEGW 256                   // elements per warp
#define CW   1024                  // windows per block
#define NWCH (LL / CW)             // 16 window chunks
#define NBCH 74                    // batch chunks (uneven 6/7-row slices)
#define NBLK (NWCH * NBCH)         // 1184 blocks = 148 SMs x 8 -> one full wave
#define NBLKP 1280                 // padded partial count (multiple of 128)
#define NVW  512                   // validity words: 16380 bits

// Deterministic scratch (no cudaMalloc allowed).
__device__ float        g_sq_blk[NBLKP];  // per-block sq partial (padding stays 0)
__device__ unsigned     g_vld_or[NVW];    // bit-per-window validity (OR-accum);
                                          // zeroed by last block each launch
__device__ unsigned int g_done;           // arrival counter; atomicInc wraps
                                          // at NBLK-1 -> self-resets per launch

__device__ __forceinline__ float sigm(float x0, float x1) {
    // softmax(x)[...,1] == sigmoid(x1-x0) == 1/(1+exp(x0-x1))
    return __fdividef(1.0f, 1.0f + __expf(x0 - x1));
}

__global__ __launch_bounds__(TPB, 8)
void bcl_fused(const float* __restrict__ pred,
               const int*   __restrict__ tgt,
               const int*   __restrict__ msk,
               float*       __restrict__ out)
{
    const int lane = threadIdx.x & 31;
    const int wrp  = threadIdx.x >> 5;
    const int seg  = blockIdx.x * CW + wrp * SEGW;  // warp's first elem/window
    const int bch  = blockIdx.y;
    const int eo   = seg + 8 * lane;                // lane's first elem/window
    const bool blk_halo = (seg + SEGW) < LL;        // halo elems exist?
    const int hofs4 = blk_halo ? (SEGW / 2) : 0;    // float4 idx of elem seg+256
    const int hofsT = blk_halo ? (SEGW / 4) : 0;    // int4 idx of elem seg+256

    // Uneven batch slice: 68 blocks x 7 rows + 6 blocks x 6 rows = 512.
    const int b0 = (bch * BB) / NBCH;
    const int b1 = ((bch + 1) * BB) / NBCH;

    float accA = 0.f, accB = 0.f;                   // windows k<4 / k>=4
    unsigned vmask = 0u;

    const size_t eb0 = (size_t)b0 * LL + seg;
    const float4* fp4 = (const float4*)(pred + 2 * eb0);
    const int4*   t4p = (const int4*)(tgt + eb0);
    const int4*   m4p = (const int4*)(msk + eb0);

    for (int bi = b0; bi < b1; bi++) {
        // Own loads: lane owns 8 consecutive elems (coalesced, 12 loads in flight).
        float4 v0 = fp4[4 * lane];
        float4 v1 = fp4[4 * lane + 1];
        float4 v2 = fp4[4 * lane + 2];
        float4 v3 = fp4[4 * lane + 3];
        int4   tv0 = t4p[2 * lane],     tv1 = t4p[2 * lane + 1];
        int4   mv0 = m4p[2 * lane],     mv1 = m4p[2 * lane + 1];
        // Warp-edge halo (uniform broadcast loads; used only by lane 31).
        float4 hv0 = fp4[hofs4], hv1 = fp4[hofs4 + 1];
        int4   htv = t4p[hofsT], hmv = m4p[hofsT];
        if (!blk_halo) { hmv.x = 0; hmv.y = 0; hmv.z = 0; hmv.w = 0; }

        // Derived per element: p = sigmoid; mm = m + 32*(t&m); pm = p*m; q = p^2*m
        float p[8], mm[8], pm[8], q[8];
        p[0] = sigm(v0.x, v0.y); p[1] = sigm(v0.z, v0.w);
        p[2] = sigm(v1.x, v1.y); p[3] = sigm(v1.z, v1.w);
        p[4] = sigm(v2.x, v2.y); p[5] = sigm(v2.z, v2.w);
        p[6] = sigm(v3.x, v3.y); p[7] = sigm(v3.z, v3.w);
        const int tt[8] = {tv0.x, tv0.y, tv0.z, tv0.w, tv1.x, tv1.y, tv1.z, tv1.w};
        const int mi[8] = {mv0.x, mv0.y, mv0.z, mv0.w, mv1.x, mv1.y, mv1.z, mv1.w};
#pragma unroll
        for (int e = 0; e < 8; e++) {
            mm[e] = (float)(mi[e] + ((tt[e] & mi[e]) << 5));
            pm[e] = mi[e] ? p[e] : 0.f;
            q[e]  = p[e] * pm[e];
        }

        // Neighbor's first 4 derived values via shfl (convergent).
        float nmm[4], npm[4], nq[4];
#pragma unroll
        for (int k = 0; k < 4; k++) {
            nmm[k] = __shfl_down_sync(0xffffffffu, mm[k], 1);
            npm[k] = __shfl_down_sync(0xffffffffu, pm[k], 1);
            nq[k]  = __shfl_down_sync(0xffffffffu, q[k], 1);
        }
        // Lane 31 patches its halo from the warp-edge loads.
        if (lane == 31) {
            float hp[4];
            hp[0] = sigm(hv0.x, hv0.y); hp[1] = sigm(hv0.z, hv0.w);
            hp[2] = sigm(hv1.x, hv1.y); hp[3] = sigm(hv1.z, hv1.w);
            const int ht[4] = {htv.x, htv.y, htv.z, htv.w};
            const int hm[4] = {hmv.x, hmv.y, hmv.z, hmv.w};
#pragma unroll
            for (int k = 0; k < 4; k++) {
                nmm[k] = (float)(hm[k] + ((ht[k] & hm[k]) << 5));
                npm[k] = hm[k] ? hp[k] : 0.f;
                nq[k]  = hp[k] * npm[k];
            }
        }

        // Sliding window-5 over 12 elems {mm[0..7], nmm[0..3]}, incremental.
        float smm = mm[0] + mm[1] + mm[2] + mm[3] + mm[4];
        float spm = pm[0] + pm[1] + pm[2] + pm[3] + pm[4];
        float sq  = q[0]  + q[1]  + q[2]  + q[3]  + q[4];
#pragma unroll
        for (int k = 0; k < 8; k++) {
            if (k > 0) {
                float am = (k + 4 < 8) ? mm[k + 4] : nmm[k - 4];
                float ap = (k + 4 < 8) ? pm[k + 4] : npm[k - 4];
                float aq = (k + 4 < 8) ? q[k + 4]  : nq[k - 4];
                smm += am - mm[k - 1];
                spm += ap - pm[k - 1];
                sq  += aq - q[k - 1];
            }
            // msum integer-valued: pvar = sq/denom - pmean^2; tvar = tmean(1-tmean)
            float stm   = floorf(smm * 0.03125f);
            float sm    = fmaf(-32.0f, stm, smm);
            float denom = fmaxf(sm, 1.0f);
            float rd    = __fdividef(1.0f, denom);
            float pmean = spm * rd;
            float tmean = stm * rd;
            float pvar  = fmaf(-pmean, pmean, sq * rd);
            float tvar  = fmaf(-tmean, tmean, tmean);
            float d     = pvar - tvar;
            if (k < 4) accA = fmaf(d, d, accA);
            else       accB = fmaf(d, d, accB);
            if (sm > 0.f) vmask |= (1u << k);
        }

        fp4 += (LL / 2); t4p += (LL / 4); m4p += (LL / 4);
    }

    // Tail gating: the ONLY OOB windows are eo=16376 (lane 31, warp 3,
    // block 15), positions k=4..7 — exactly accB.
    if (eo + 4 >= NW) { accB = 0.f; vmask &= 0x0Fu; }

    // Validity: one atomicOr per thread (RED.OR, order-independent ->
    // deterministic). eo is a multiple of 8, so the 8 bits never straddle.
    if (vmask)
        atomicOr(&g_vld_or[(unsigned)eo >> 5], vmask << ((unsigned)eo & 31u));
    __threadfence();   // this thread's REDs visible before block arrival

    // In-block deterministic reduction of sq -> one float per block.
    float a = accA + accB;
    a += __shfl_xor_sync(0xffffffffu, a, 16);
    a += __shfl_xor_sync(0xffffffffu, a, 8);
    a += __shfl_xor_sync(0xffffffffu, a, 4);
    a += __shfl_xor_sync(0xffffffffu, a, 2);
    a += __shfl_xor_sync(0xffffffffu, a, 1);
    __shared__ float s_red[4];
    __shared__ unsigned s_last;
    if (lane == 0) s_red[wrp] = a;
    __syncthreads();
    if (threadIdx.x == 0) {
        g_sq_blk[bch * NWCH + blockIdx.x] =
            (s_red[0] + s_red[1]) + (s_red[2] + s_red[3]);
        __threadfence();   // partial visible before arrival
        // Wrapping arrival counter: self-resets to 0 after NBLK increments.
        unsigned old = atomicInc(&g_done, NBLK - 1);
        s_last = (old == NBLK - 1) ? 1u : 0u;
    }
    __syncthreads();
    if (!s_last) return;

    // ---- Last block: final reduction (5 KB sq + 2 KB validity) ----
    __threadfence();       // acquire: all other blocks' fenced writes visible
    const int t = threadIdx.x;

    float s = 0.f;
#pragma unroll
    for (int i = 0; i < NBLKP / 128; i++)
        s += g_sq_blk[t + 128 * i];            // padding reads are 0

    uint4 vv = ((const uint4*)g_vld_or)[t];    // 512 words / 128 thr
    int c = __popc(vv.x) + __popc(vv.y) + __popc(vv.z) + __popc(vv.w);
    // Zero validity accumulator for the next graph replay.
    ((uint4*)g_vld_or)[t] = make_uint4(0u, 0u, 0u, 0u);

    // Block reduce s and c.
    s += __shfl_xor_sync(0xffffffffu, s, 16);
    s += __shfl_xor_sync(0xffffffffu, s, 8);
    s += __shfl_xor_sync(0xffffffffu, s, 4);
    s += __shfl_xor_sync(0xffffffffu, s, 2);
    s += __shfl_xor_sync(0xffffffffu, s, 1);
    c += __shfl_xor_sync(0xffffffffu, c, 16);
    c += __shfl_xor_sync(0xffffffffu, c, 8);
    c += __shfl_xor_sync(0xffffffffu, c, 4);
    c += __shfl_xor_sync(0xffffffffu, c, 2);
    c += __shfl_xor_sync(0xffffffffu, c, 1);
    __shared__ float fs[4];
    __shared__ int   fc[4];
    if (lane == 0) { fs[wrp] = s; fc[wrp] = c; }
    __syncthreads();
    if (t == 0) {
        float S = (fs[0] + fs[1]) + (fs[2] + fs[3]);
        int   C = (fc[0] + fc[1]) + (fc[2] + fc[3]);
        out[0] = S * (1.0f / (float)BB) / fmaxf((float)C, 1.0f);
    }
}

extern "C" void kernel_launch(void* const* d_in, const int* in_sizes, int n_in,
                              void* d_out, int out_size)
{
    const float* pred = (const float*)d_in[0];   // [512, 16384, 2] f32
    const int*   tgt  = (const int*)d_in[1];     // [512, 16384] i32
    const int*   msk  = (const int*)d_in[2];     // [512, 16384] i32

    dim3 grid(NWCH, NBCH);                        // 16 x 74 = 1184 = 148 x 8
    bcl_fused<<<grid, TPB>>>(pred, tgt, msk, (float*)d_out);
}